// round 15
// baseline (speedup 1.0000x reference)
#include <cuda_runtime.h>
#include <cuda_fp16.h>
#include <stdint.h>

// Problem constants (fixed by the dataset)
#define NNODES 100000
#define NEDGES 1600000
#define INC    128
#define HID    64
#define OUTC   32

#define SCAN_B 512
#define NSCANB ((NNODES + SCAN_B - 1) / SCAN_B)   // 196
#define MAXD   512                                 // degree bins for counting sort

// ---------------------------------------------------------------------------
// Static scratch — 20.80 MB (equal to the R9 known-pass footprint).
// t' (fp16) lives in d_out.
// ---------------------------------------------------------------------------
__device__ __align__(16) __half g_h[(size_t)NNODES * HID]; // h' (12.8 MB)
__device__ __align__(16) int    g_srcx[NEDGES];            // CSR src (6.4 MB)
__device__ __align__(16) float  g_dinv[NNODES];
__device__ __align__(16) int    g_deg[NNODES];             // histogram, then fill cursor
__device__ __align__(16) int    g_off[NNODES + 1];         // CSR offsets (off[N]=E)
__device__ __align__(16) int    g_perm[NNODES];            // nodes sorted by degree
__device__ __align__(16) int    g_hist[MAXD];              // degree-value histogram/base
__device__              int     g_bsum[NSCANB];

// ---------------------------------------------------------------------------
// Prep
// ---------------------------------------------------------------------------
__global__ __launch_bounds__(256) void k_zero() {
    int i = blockIdx.x * blockDim.x + threadIdx.x;
    if (i < NNODES) g_deg[i] = 0;
    if (i < MAXD)   g_hist[i] = 0;
}

// 4 edges per thread (int4 read of dst half)
__global__ __launch_bounds__(256) void k_deg(const int* __restrict__ ei) {
    int e4 = blockIdx.x * blockDim.x + threadIdx.x;
    if (e4 >= NEDGES / 4) return;
    int4 d = ((const int4*)(ei + NEDGES))[e4];
    atomicAdd(&g_deg[min(max(d.x, 0), NNODES - 1)], 1);
    atomicAdd(&g_deg[min(max(d.y, 0), NNODES - 1)], 1);
    atomicAdd(&g_deg[min(max(d.z, 0), NNODES - 1)], 1);
    atomicAdd(&g_deg[min(max(d.w, 0), NNODES - 1)], 1);
}

// scan1 also computes dinv = rsqrt(deg+1) and the degree-value histogram
__global__ __launch_bounds__(SCAN_B) void k_scan1() {
    __shared__ int s[SCAN_B];
    int i = blockIdx.x * SCAN_B + threadIdx.x;
    int v = (i < NNODES) ? g_deg[i] : 0;
    if (i < NNODES) {
        g_dinv[i] = rsqrtf((float)v + 1.0f);
        atomicAdd(&g_hist[min(v, MAXD - 1)], 1);
    }
    s[threadIdx.x] = v;
    __syncthreads();
    #pragma unroll
    for (int ofs = 1; ofs < SCAN_B; ofs <<= 1) {
        int t = (threadIdx.x >= ofs) ? s[threadIdx.x - ofs] : 0;
        __syncthreads();
        s[threadIdx.x] += t;
        __syncthreads();
    }
    if (i < NNODES) g_off[i] = s[threadIdx.x] - v;
    if (threadIdx.x == SCAN_B - 1) g_bsum[blockIdx.x] = s[SCAN_B - 1];
}

__global__ void k_scan2() {
    if (threadIdx.x == 0 && blockIdx.x == 0) {
        int run = 0;
        for (int b = 0; b < NSCANB; b++) { int t = g_bsum[b]; g_bsum[b] = run; run += t; }
    }
}

__global__ __launch_bounds__(256) void k_scan3() {
    int i = blockIdx.x * blockDim.x + threadIdx.x;
    if (i < NNODES) g_off[i] += g_bsum[i / SCAN_B];
    if (i == 0) g_off[NNODES] = NEDGES;
}

// exclusive scan of the 512-bin degree histogram (single block)
__global__ __launch_bounds__(MAXD) void k_hscan() {
    __shared__ int s[MAXD];
    int i = threadIdx.x;
    int v = g_hist[i];
    s[i] = v;
    __syncthreads();
    #pragma unroll
    for (int ofs = 1; ofs < MAXD; ofs <<= 1) {
        int t = (i >= ofs) ? s[i - ofs] : 0;
        __syncthreads();
        s[i] += t;
        __syncthreads();
    }
    g_hist[i] = s[i] - v;   // exclusive base per bin
}

// scatter nodes into degree-sorted order (bases consumed by atomicAdd)
__global__ __launch_bounds__(256) void k_perm() {
    int i = blockIdx.x * blockDim.x + threadIdx.x;
    if (i >= NNODES) return;
    int bin = min(g_deg[i], MAXD - 1);
    int pos = atomicAdd(&g_hist[bin], 1);
    g_perm[pos] = i;
}

// Fill: cursor = countdown on g_deg (dead afterwards). 2 edges per thread.
__global__ __launch_bounds__(256) void k_fill(const int* __restrict__ ei) {
    int e2 = blockIdx.x * blockDim.x + threadIdx.x;
    if (e2 >= NEDGES / 2) return;
    int2 s = ((const int2*)ei)[e2];
    int2 d = ((const int2*)(ei + NEDGES))[e2];
    {
        int ss = min(max(s.x, 0), NNODES - 1);
        int dd = min(max(d.x, 0), NNODES - 1);
        int pos = atomicSub(&g_deg[dd], 1) - 1;
        g_srcx[g_off[dd] + pos] = ss;
    }
    {
        int ss = min(max(s.y, 0), NNODES - 1);
        int dd = min(max(d.y, 0), NNODES - 1);
        int pos = atomicSub(&g_deg[dd], 1) - 1;
        g_srcx[g_off[dd] + pos] = ss;
    }
}

// ---------------------------------------------------------------------------
// K5: t' = (x @ W0) * dinv[row] -> d_out as fp16.
// 5 x-tiles of 16 rows looped over ONE staged W0 (80 rows/block; 100000=80*1250).
// ---------------------------------------------------------------------------
#define XPAD 132
#define ROWT 16
#define TILES 5
__global__ __launch_bounds__(256) void k_gemm1(const float* __restrict__ x,
                                               const float* __restrict__ W0,
                                               __half* __restrict__ tp) {
    __shared__ float sW[INC * HID];   // 32 KB
    __shared__ float sX[ROWT * XPAD]; // 8.4 KB
    int tid  = threadIdx.x;
    int base = blockIdx.x * (ROWT * TILES);

    {
        float4*       sW4 = (float4*)sW;
        const float4* W4  = (const float4*)W0;
        #pragma unroll
        for (int i = tid; i < INC * HID / 4; i += 256) sW4[i] = W4[i];
    }

    int r  = tid >> 4;     // 0..15 row in tile
    int cg = tid & 15;     // 0..15 col group (4 cols)

    for (int t = 0; t < TILES; t++) {
        int row0 = base + t * ROWT;
        __syncthreads();
        for (int i = tid; i < ROWT * (INC / 4); i += 256) {
            int rr = i >> 5, q = i & 31;
            *(float4*)(sX + rr * XPAD + q * 4) =
                ((const float4*)(x + (size_t)(row0 + rr) * INC))[q];
        }
        __syncthreads();

        float4 acc = make_float4(0.0f, 0.0f, 0.0f, 0.0f);
        const float* xr = sX + r * XPAD;
        #pragma unroll 8
        for (int k = 0; k < INC; k++) {
            float  xv = xr[k];
            float4 w  = *(const float4*)(sW + k * HID + cg * 4);
            acc.x += xv * w.x; acc.y += xv * w.y;
            acc.z += xv * w.z; acc.w += xv * w.w;
        }

        int row = row0 + r;
        float dv = g_dinv[row];
        __half2 p0 = __floats2half2_rn(acc.x * dv, acc.y * dv);
        __half2 p1 = __floats2half2_rn(acc.z * dv, acc.w * dv);
        uint2 pk = make_uint2(*(unsigned*)&p0, *(unsigned*)&p1);
        ((uint2*)tp)[(size_t)row * 16 + cg] = pk;
    }
}

// ---------------------------------------------------------------------------
// fp16 helpers
// ---------------------------------------------------------------------------
__device__ __forceinline__ void unpack8(uint4 r, float* f) {
    __half2 h;
    *(unsigned*)&h = r.x; float2 t = __half22float2(h); f[0] = t.x; f[1] = t.y;
    *(unsigned*)&h = r.y; t = __half22float2(h);        f[2] = t.x; f[3] = t.y;
    *(unsigned*)&h = r.z; t = __half22float2(h);        f[4] = t.x; f[5] = t.y;
    *(unsigned*)&h = r.w; t = __half22float2(h);        f[6] = t.x; f[7] = t.y;
}

// 4-wide unrolled CSR gather accumulate (8 halves per thread)
__device__ __forceinline__ void gather_sum(const uint4* __restrict__ H,
                                           int beg, int end, int j, float* a) {
    float f[8];
    int k = beg;
    int n4 = beg + ((end - beg) & ~3);
    for (; k < n4; k += 4) {
        int s0 = g_srcx[k];
        int s1 = g_srcx[k + 1];
        int s2 = g_srcx[k + 2];
        int s3 = g_srcx[k + 3];
        uint4 r0 = H[(size_t)s0 * 8 + j];
        uint4 r1 = H[(size_t)s1 * 8 + j];
        uint4 r2 = H[(size_t)s2 * 8 + j];
        uint4 r3 = H[(size_t)s3 * 8 + j];
        unpack8(r0, f);
        #pragma unroll
        for (int i = 0; i < 8; i++) a[i] += f[i];
        unpack8(r1, f);
        #pragma unroll
        for (int i = 0; i < 8; i++) a[i] += f[i];
        unpack8(r2, f);
        #pragma unroll
        for (int i = 0; i < 8; i++) a[i] += f[i];
        unpack8(r3, f);
        #pragma unroll
        for (int i = 0; i < 8; i++) a[i] += f[i];
    }
    for (; k < end; k++) {
        uint4 r0 = H[(size_t)g_srcx[k] * 8 + j];
        unpack8(r0, f);
        #pragma unroll
        for (int i = 0; i < 8; i++) a[i] += f[i];
    }
}

// ---------------------------------------------------------------------------
// K6: layer-1 gather (fp16 in/out), degree-sorted via g_perm.
// h'[n] = relu(dinv*(sum t'[src] + t'[n]) + b0)*dinv, fp32 accumulate.
// ---------------------------------------------------------------------------
__global__ __launch_bounds__(256) void k_agg1(const uint4* __restrict__ tp,
                                              const float* __restrict__ b0) {
    unsigned gid = blockIdx.x * blockDim.x + threadIdx.x;
    if (gid >= (unsigned)NNODES * 8u) return;
    int node = g_perm[gid >> 3];
    int j    = gid & 7;

    float a[8];
    unpack8(tp[(size_t)node * 8 + j], a);   // self (pre-scaled)
    gather_sum(tp, g_off[node], g_off[node + 1], j, a);

    float dv = g_dinv[node];
    const float* bp = b0 + j * 8;
    #pragma unroll
    for (int i = 0; i < 8; i++)
        a[i] = fmaxf(a[i] * dv + bp[i], 0.0f) * dv;

    __half2 p0 = __floats2half2_rn(a[0], a[1]);
    __half2 p1 = __floats2half2_rn(a[2], a[3]);
    __half2 p2 = __floats2half2_rn(a[4], a[5]);
    __half2 p3 = __floats2half2_rn(a[6], a[7]);
    uint4 pk = make_uint4(*(unsigned*)&p0, *(unsigned*)&p1,
                          *(unsigned*)&p2, *(unsigned*)&p3);
    ((uint4*)g_h)[(size_t)node * 8 + j] = pk;
}

// ---------------------------------------------------------------------------
// K7 (fused): layer-2/3 gather (fp16, degree-sorted) + output GEMM.
// 32 perm-nodes per block; per-group writes stay 128B-contiguous.
// ---------------------------------------------------------------------------
#define GP2 68
__global__ __launch_bounds__(256) void k_agg2out(const float* __restrict__ Wm,
                                                 const float* __restrict__ bm,
                                                 const float* __restrict__ Wl,
                                                 const float* __restrict__ bl,
                                                 float* __restrict__ out) {
    __shared__ float sW[HID * 64];   // 16 KB combined [64k][64m]
    __shared__ float sB[64];
    __shared__ float sG[32 * GP2];   // 8.5 KB
    int tid   = threadIdx.x;
    int node0 = blockIdx.x * 32;
    int nl    = tid >> 3;            // 0..31 perm-slot in block
    int j     = tid & 7;             // 0..7

    for (int i = tid; i < HID * OUTC; i += 256) {
        int k = i / OUTC, m = i % OUTC;
        sW[k * 64 + m]      = Wm[i];
        sW[k * 64 + 32 + m] = Wl[i];
    }
    if (tid < 32) { sB[tid] = bm[tid]; sB[32 + tid] = bl[tid]; }

    int node = g_perm[node0 + nl];

    // Phase 1: gather 8 channels per thread
    {
        const uint4* H = (const uint4*)g_h;
        float a[8];
        unpack8(H[(size_t)node * 8 + j], a);    // self
        gather_sum(H, g_off[node], g_off[node + 1], j, a);

        float dv = g_dinv[node];
        float* gs = sG + nl * GP2 + j * 8;
        *(float4*)(gs + 0) = make_float4(a[0]*dv, a[1]*dv, a[2]*dv, a[3]*dv);
        *(float4*)(gs + 4) = make_float4(a[4]*dv, a[5]*dv, a[6]*dv, a[7]*dv);
    }
    __syncthreads();

    // Phase 2: mini-GEMM, 8 output cols per thread (c0 = j*8), contraction 64.
    {
        int c0 = j * 8;
        float acc[8];
        #pragma unroll
        for (int m = 0; m < 8; m++) acc[m] = sB[c0 + m];
        const float* gr = sG + nl * GP2;
        #pragma unroll 8
        for (int k = 0; k < HID; k++) {
            float gv = gr[k];
            const float* wr = sW + k * 64 + c0;
            #pragma unroll
            for (int m = 0; m < 8; m++) acc[m] += gv * wr[m];
        }
        float* dst = (c0 < 32)
            ? out + (size_t)node * OUTC + c0
            : out + (size_t)NNODES * OUTC + (size_t)node * OUTC + (c0 - 32);
        *(float4*)(dst + 0) = make_float4(acc[0], acc[1], acc[2], acc[3]);
        *(float4*)(dst + 4) = make_float4(acc[4], acc[5], acc[6], acc[7]);
    }
}

// ---------------------------------------------------------------------------
// Pre-main warmup (fault-tolerant; no allocation APIs)
// ---------------------------------------------------------------------------
namespace {
struct Warmup {
    Warmup() {
        if (cudaSetDevice(0) != cudaSuccess) return;
        k_zero<<<1, 32>>>();
        k_scan2<<<1, 32>>>();
        if (cudaGetLastError() != cudaSuccess) return;
        cudaStreamSynchronize(0);
    }
};
static Warmup s_warmup;
}  // namespace

// ---------------------------------------------------------------------------
// Launcher
// ---------------------------------------------------------------------------
extern "C" void kernel_launch(void* const* d_in, const int* in_sizes, int n_in,
                              void* d_out, int out_size) {
    const float* x  = (const float*)d_in[0];
    const int*   ei = (const int*)d_in[1];
    const float* W0 = (const float*)d_in[2];
    const float* b0 = (const float*)d_in[3];
    const float* Wm = (const float*)d_in[4];
    const float* bm = (const float*)d_in[5];
    const float* Wl = (const float*)d_in[6];
    const float* bl = (const float*)d_in[7];
    float*       out = (float*)d_out;

    const int TB = 256;
    const int gN   = (NNODES + TB - 1) / TB;               // 391
    const int gE4  = (NEDGES / 4 + TB - 1) / TB;           // 1563
    const int gE2  = (NEDGES / 2 + TB - 1) / TB;           // 3125
    const int gG1  = NNODES / (ROWT * TILES);              // 1250
    const int gA1  = (NNODES * 8 + TB - 1) / TB;           // 3125
    const int gA2  = (NNODES + 31) / 32;                   // 3125

    k_zero<<<gN, TB>>>();
    k_deg<<<gE4, TB>>>(ei);
    k_scan1<<<NSCANB, SCAN_B>>>();
    k_scan2<<<1, 32>>>();
    k_scan3<<<gN, TB>>>();
    k_hscan<<<1, MAXD>>>();
    k_perm<<<gN, TB>>>();
    k_fill<<<gE2, TB>>>(ei);
    k_gemm1<<<gG1, TB>>>(x, W0, (__half*)out);             // t' (fp16) -> d_out
    k_agg1<<<gA1, TB>>>((const uint4*)out, b0);            // h' (fp16) -> g_h
    k_agg2out<<<gA2, TB>>>(Wm, bm, Wl, bl, out);
}

// round 17
// speedup vs baseline: 1.1364x; 1.1364x over previous
#include <cuda_runtime.h>
#include <cuda_fp16.h>
#include <stdint.h>

// Problem constants (fixed by the dataset)
#define NNODES 100000
#define NEDGES 1600000
#define INC    128
#define HID    64
#define OUTC   32

#define SCAN_B 512
#define NSCANB ((NNODES + SCAN_B - 1) / SCAN_B)   // 196

// ---------------------------------------------------------------------------
// Static scratch — 20.4 MB (known-pass envelope). t' (fp16) lives in d_out.
// Natural node order everywhere (R15's degree-sort destroyed coalescing).
// NOTE: byte-identical resubmission of the Round-16 kernel — the bench died
// at the broker (container failed twice) before compiling or running it.
// ---------------------------------------------------------------------------
__device__ __align__(16) __half g_h[(size_t)NNODES * HID]; // h' (12.8 MB)
__device__ __align__(16) int    g_srcx[NEDGES];            // CSR src (6.4 MB)
__device__ __align__(16) float  g_dinv[NNODES];
__device__ __align__(16) int    g_deg[NNODES];             // histogram, then fill cursor
__device__ __align__(16) int    g_off[NNODES + 1];         // CSR offsets (off[N]=E)
__device__              int     g_bsum[NSCANB];

// ---------------------------------------------------------------------------
// Prep
// ---------------------------------------------------------------------------
__global__ __launch_bounds__(256) void k_zero() {
    int i = blockIdx.x * blockDim.x + threadIdx.x;
    if (i < NNODES) g_deg[i] = 0;
}

// 4 edges per thread (int4 read of dst half)
__global__ __launch_bounds__(256) void k_deg(const int* __restrict__ ei) {
    int e4 = blockIdx.x * blockDim.x + threadIdx.x;
    if (e4 >= NEDGES / 4) return;
    int4 d = ((const int4*)(ei + NEDGES))[e4];
    atomicAdd(&g_deg[min(max(d.x, 0), NNODES - 1)], 1);
    atomicAdd(&g_deg[min(max(d.y, 0), NNODES - 1)], 1);
    atomicAdd(&g_deg[min(max(d.z, 0), NNODES - 1)], 1);
    atomicAdd(&g_deg[min(max(d.w, 0), NNODES - 1)], 1);
}

// scan1 also computes dinv = rsqrt(deg+1)
__global__ __launch_bounds__(SCAN_B) void k_scan1() {
    __shared__ int s[SCAN_B];
    int i = blockIdx.x * SCAN_B + threadIdx.x;
    int v = (i < NNODES) ? g_deg[i] : 0;
    if (i < NNODES) g_dinv[i] = rsqrtf((float)v + 1.0f);
    s[threadIdx.x] = v;
    __syncthreads();
    #pragma unroll
    for (int ofs = 1; ofs < SCAN_B; ofs <<= 1) {
        int t = (threadIdx.x >= ofs) ? s[threadIdx.x - ofs] : 0;
        __syncthreads();
        s[threadIdx.x] += t;
        __syncthreads();
    }
    if (i < NNODES) g_off[i] = s[threadIdx.x] - v;
    if (threadIdx.x == SCAN_B - 1) g_bsum[blockIdx.x] = s[SCAN_B - 1];
}

__global__ void k_scan2() {
    if (threadIdx.x == 0 && blockIdx.x == 0) {
        int run = 0;
        for (int b = 0; b < NSCANB; b++) { int t = g_bsum[b]; g_bsum[b] = run; run += t; }
    }
}

__global__ __launch_bounds__(256) void k_scan3() {
    int i = blockIdx.x * blockDim.x + threadIdx.x;
    if (i < NNODES) g_off[i] += g_bsum[i / SCAN_B];
    if (i == 0) g_off[NNODES] = NEDGES;
}

// Fill: cursor = countdown on g_deg (dead afterwards). 2 edges per thread.
__global__ __launch_bounds__(256) void k_fill(const int* __restrict__ ei) {
    int e2 = blockIdx.x * blockDim.x + threadIdx.x;
    if (e2 >= NEDGES / 2) return;
    int2 s = ((const int2*)ei)[e2];
    int2 d = ((const int2*)(ei + NEDGES))[e2];
    {
        int ss = min(max(s.x, 0), NNODES - 1);
        int dd = min(max(d.x, 0), NNODES - 1);
        int pos = atomicSub(&g_deg[dd], 1) - 1;
        g_srcx[g_off[dd] + pos] = ss;
    }
    {
        int ss = min(max(s.y, 0), NNODES - 1);
        int dd = min(max(d.y, 0), NNODES - 1);
        int pos = atomicSub(&g_deg[dd], 1) - 1;
        g_srcx[g_off[dd] + pos] = ss;
    }
}

// ---------------------------------------------------------------------------
// K5: t' = (x @ W0) * dinv[row] -> d_out as fp16.
// 5 x-tiles of 16 rows looped over ONE staged W0 (80 rows/block; 100000=80*1250).
// ---------------------------------------------------------------------------
#define XPAD 132
#define ROWT 16
#define TILES 5
__global__ __launch_bounds__(256) void k_gemm1(const float* __restrict__ x,
                                               const float* __restrict__ W0,
                                               __half* __restrict__ tp) {
    __shared__ float sW[INC * HID];   // 32 KB
    __shared__ float sX[ROWT * XPAD]; // 8.4 KB
    int tid  = threadIdx.x;
    int base = blockIdx.x * (ROWT * TILES);

    {
        float4*       sW4 = (float4*)sW;
        const float4* W4  = (const float4*)W0;
        #pragma unroll
        for (int i = tid; i < INC * HID / 4; i += 256) sW4[i] = W4[i];
    }

    int r  = tid >> 4;     // 0..15 row in tile
    int cg = tid & 15;     // 0..15 col group (4 cols)

    for (int t = 0; t < TILES; t++) {
        int row0 = base + t * ROWT;
        __syncthreads();
        for (int i = tid; i < ROWT * (INC / 4); i += 256) {
            int rr = i >> 5, q = i & 31;
            *(float4*)(sX + rr * XPAD + q * 4) =
                ((const float4*)(x + (size_t)(row0 + rr) * INC))[q];
        }
        __syncthreads();

        float4 acc = make_float4(0.0f, 0.0f, 0.0f, 0.0f);
        const float* xr = sX + r * XPAD;
        #pragma unroll 8
        for (int k = 0; k < INC; k++) {
            float  xv = xr[k];
            float4 w  = *(const float4*)(sW + k * HID + cg * 4);
            acc.x += xv * w.x; acc.y += xv * w.y;
            acc.z += xv * w.z; acc.w += xv * w.w;
        }

        int row = row0 + r;
        float dv = g_dinv[row];
        __half2 p0 = __floats2half2_rn(acc.x * dv, acc.y * dv);
        __half2 p1 = __floats2half2_rn(acc.z * dv, acc.w * dv);
        uint2 pk = make_uint2(*(unsigned*)&p0, *(unsigned*)&p1);
        ((uint2*)tp)[(size_t)row * 16 + cg] = pk;
    }
}

// ---------------------------------------------------------------------------
// fp16 helpers
// ---------------------------------------------------------------------------
__device__ __forceinline__ void unpack8(uint4 r, float* f) {
    __half2 h;
    *(unsigned*)&h = r.x; float2 t = __half22float2(h); f[0] = t.x; f[1] = t.y;
    *(unsigned*)&h = r.y; t = __half22float2(h);        f[2] = t.x; f[3] = t.y;
    *(unsigned*)&h = r.z; t = __half22float2(h);        f[4] = t.x; f[5] = t.y;
    *(unsigned*)&h = r.w; t = __half22float2(h);        f[6] = t.x; f[7] = t.y;
}

// 4-wide unrolled CSR gather accumulate (8 halves per thread) — MLP=4
__device__ __forceinline__ void gather_sum(const uint4* __restrict__ H,
                                           int beg, int end, int j, float* a) {
    float f[8];
    int k = beg;
    int n4 = beg + ((end - beg) & ~3);
    for (; k < n4; k += 4) {
        int s0 = g_srcx[k];
        int s1 = g_srcx[k + 1];
        int s2 = g_srcx[k + 2];
        int s3 = g_srcx[k + 3];
        uint4 r0 = H[(size_t)s0 * 8 + j];
        uint4 r1 = H[(size_t)s1 * 8 + j];
        uint4 r2 = H[(size_t)s2 * 8 + j];
        uint4 r3 = H[(size_t)s3 * 8 + j];
        unpack8(r0, f);
        #pragma unroll
        for (int i = 0; i < 8; i++) a[i] += f[i];
        unpack8(r1, f);
        #pragma unroll
        for (int i = 0; i < 8; i++) a[i] += f[i];
        unpack8(r2, f);
        #pragma unroll
        for (int i = 0; i < 8; i++) a[i] += f[i];
        unpack8(r3, f);
        #pragma unroll
        for (int i = 0; i < 8; i++) a[i] += f[i];
    }
    for (; k < end; k++) {
        uint4 r0 = H[(size_t)g_srcx[k] * 8 + j];
        unpack8(r0, f);
        #pragma unroll
        for (int i = 0; i < 8; i++) a[i] += f[i];
    }
}

// ---------------------------------------------------------------------------
// K6: layer-1 gather (fp16 in/out), natural node order (coalesced).
// h'[n] = relu(dinv*(sum t'[src] + t'[n]) + b0)*dinv, fp32 accumulate.
// Thread = (node, j in 0..7): one uint4 (8 halves).
// ---------------------------------------------------------------------------
__global__ __launch_bounds__(256) void k_agg1(const uint4* __restrict__ tp,
                                              const float* __restrict__ b0) {
    unsigned gid = blockIdx.x * blockDim.x + threadIdx.x;
    if (gid >= (unsigned)NNODES * 8u) return;
    int node = gid >> 3;
    int j    = gid & 7;

    float a[8];
    unpack8(tp[(size_t)node * 8 + j], a);   // self (pre-scaled)
    gather_sum(tp, g_off[node], g_off[node + 1], j, a);

    float dv = g_dinv[node];
    const float* bp = b0 + j * 8;
    #pragma unroll
    for (int i = 0; i < 8; i++)
        a[i] = fmaxf(a[i] * dv + bp[i], 0.0f) * dv;

    __half2 p0 = __floats2half2_rn(a[0], a[1]);
    __half2 p1 = __floats2half2_rn(a[2], a[3]);
    __half2 p2 = __floats2half2_rn(a[4], a[5]);
    __half2 p3 = __floats2half2_rn(a[6], a[7]);
    uint4 pk = make_uint4(*(unsigned*)&p0, *(unsigned*)&p1,
                          *(unsigned*)&p2, *(unsigned*)&p3);
    ((uint4*)g_h)[(size_t)node * 8 + j] = pk;
}

// ---------------------------------------------------------------------------
// K7 (fused): layer-2/3 gather (fp16) + output GEMM. 32 nodes per block.
// Phase 1 (8 thr/node, 8 ch each): g[n] = dinv*(sum h'[src] + h'[n]) -> smem.
// Phase 2 (8 thr/node, 8 cols each): out = g @ [Wm|Wl] + [bm|bl].
// ---------------------------------------------------------------------------
#define GP2 68
__global__ __launch_bounds__(256) void k_agg2out(const float* __restrict__ Wm,
                                                 const float* __restrict__ bm,
                                                 const float* __restrict__ Wl,
                                                 const float* __restrict__ bl,
                                                 float* __restrict__ out) {
    __shared__ float sW[HID * 64];   // 16 KB combined [64k][64m]
    __shared__ float sB[64];
    __shared__ float sG[32 * GP2];   // 8.5 KB
    int tid   = threadIdx.x;
    int node0 = blockIdx.x * 32;
    int nl    = tid >> 3;            // 0..31 node in block
    int j     = tid & 7;             // 0..7

    for (int i = tid; i < HID * OUTC; i += 256) {
        int k = i / OUTC, m = i % OUTC;
        sW[k * 64 + m]      = Wm[i];
        sW[k * 64 + 32 + m] = Wl[i];
    }
    if (tid < 32) { sB[tid] = bm[tid]; sB[32 + tid] = bl[tid]; }

    int node = node0 + nl;

    // Phase 1: gather 8 channels (one uint4 = 8 halves) per thread
    {
        const uint4* H = (const uint4*)g_h;
        float a[8];
        unpack8(H[(size_t)node * 8 + j], a);    // self
        gather_sum(H, g_off[node], g_off[node + 1], j, a);

        float dv = g_dinv[node];
        float* gs = sG + nl * GP2 + j * 8;
        *(float4*)(gs + 0) = make_float4(a[0]*dv, a[1]*dv, a[2]*dv, a[3]*dv);
        *(float4*)(gs + 4) = make_float4(a[4]*dv, a[5]*dv, a[6]*dv, a[7]*dv);
    }
    __syncthreads();

    // Phase 2: mini-GEMM, 8 output cols per thread (c0 = j*8), contraction 64.
    {
        int c0 = j * 8;
        float acc[8];
        #pragma unroll
        for (int m = 0; m < 8; m++) acc[m] = sB[c0 + m];
        const float* gr = sG + nl * GP2;
        #pragma unroll 8
        for (int k = 0; k < HID; k++) {
            float gv = gr[k];
            const float* wr = sW + k * 64 + c0;
            #pragma unroll
            for (int m = 0; m < 8; m++) acc[m] += gv * wr[m];
        }
        float* dst = (c0 < 32)
            ? out + (size_t)node * OUTC + c0
            : out + (size_t)NNODES * OUTC + (size_t)node * OUTC + (c0 - 32);
        *(float4*)(dst + 0) = make_float4(acc[0], acc[1], acc[2], acc[3]);
        *(float4*)(dst + 4) = make_float4(acc[4], acc[5], acc[6], acc[7]);
    }
}

// ---------------------------------------------------------------------------
// Pre-main warmup (fault-tolerant; no allocation APIs)
// ---------------------------------------------------------------------------
namespace {
struct Warmup {
    Warmup() {
        if (cudaSetDevice(0) != cudaSuccess) return;
        k_zero<<<1, 32>>>();
        k_scan2<<<1, 32>>>();
        if (cudaGetLastError() != cudaSuccess) return;
        cudaStreamSynchronize(0);
    }
};
static Warmup s_warmup;
}  // namespace

// ---------------------------------------------------------------------------
// Launcher
// ---------------------------------------------------------------------------
extern "C" void kernel_launch(void* const* d_in, const int* in_sizes, int n_in,
                              void* d_out, int out_size) {
    const float* x  = (const float*)d_in[0];
    const int*   ei = (const int*)d_in[1];
    const float* W0 = (const float*)d_in[2];
    const float* b0 = (const float*)d_in[3];
    const float* Wm = (const float*)d_in[4];
    const float* bm = (const float*)d_in[5];
    const float* Wl = (const float*)d_in[6];
    const float* bl = (const float*)d_in[7];
    float*       out = (float*)d_out;

    const int TB = 256;
    const int gN   = (NNODES + TB - 1) / TB;               // 391
    const int gE4  = (NEDGES / 4 + TB - 1) / TB;           // 1563
    const int gE2  = (NEDGES / 2 + TB - 1) / TB;           // 3125
    const int gG1  = NNODES / (ROWT * TILES);              // 1250
    const int gA1  = (NNODES * 8 + TB - 1) / TB;           // 3125
    const int gA2  = (NNODES + 31) / 32;                   // 3125

    k_zero<<<gN, TB>>>();
    k_deg<<<gE4, TB>>>(ei);
    k_scan1<<<NSCANB, SCAN_B>>>();
    k_scan2<<<1, 32>>>();
    k_scan3<<<gN, TB>>>();
    k_fill<<<gE2, TB>>>(ei);
    k_gemm1<<<gG1, TB>>>(x, W0, (__half*)out);             // t' (fp16) -> d_out
    k_agg1<<<gA1, TB>>>((const uint4*)out, b0);            // h' (fp16) -> g_h
    k_agg2out<<<gA2, TB>>>(Wm, bm, Wl, bl, out);
}